// round 7
// baseline (speedup 1.0000x reference)
#include <cuda_runtime.h>

// SingleDisCoLoss: BCE + 0.1 * weighted dcorr^2 over labels==0 subset. N=8192.
// Round 7: R5 structure (3 launches, slim k_pab w/ last-block finalize) +
//          R6's atomics-free k_prep; k_uv rebuilds bucket sums from member lists.
//   P_aa,P_bb closed form; u,v exact via monotone 256-bucket prefix sums;
//   S_XY = P_xy + (2W-4nf)/nf^2 * Q_xy + xt*yt*(4nf^2-4W nf+W^2)

#define MAXN 8192
#define NB   256
#define CAP  256
#define TB4  128
#define ROWS 4
#define GY   64
#define GX   (MAXN / (TB4 * ROWS))          // 16
#define NBLK (GX * GY)                      // 1024
#define K1B  32
#define K1T  256
#define DISCO_LAMBDA 0.1
#define ABSMASK 0x7FFFFFFF7FFFFFFFULL

typedef unsigned long long ull;

// ---- scratch (device globals; zero at load; re-zeroed by finalize path) ----
__device__ float  g_wm[MAXN];
__device__ int    g_cntp[NB], g_cntt[NB];
__device__ float2 g_mp[NB * CAP], g_mt[NB * CAP];   // {value, wm}
__device__ double g_part[7][K1B];   // bce, nf, W, Sp, Sp2, St, St2
__device__ double g_S[5];           // sa, sb, qab, qaa, qbb (atomic)
__device__ double g_Pab;            // atomic
__device__ unsigned g_ticket;

// ---- helpers --------------------------------------------------------------
__device__ __forceinline__ ull pack2(float a, float b) {
    ull r; asm("mov.b64 %0, {%1, %2};" : "=l"(r) : "f"(a), "f"(b)); return r;
}
__device__ __forceinline__ float lo2(ull x) { return __uint_as_float((unsigned)x); }
__device__ __forceinline__ float hi2(ull x) { return __uint_as_float((unsigned)(x >> 32)); }
#define ADD2(out, a, b) asm("add.rn.f32x2 %0, %1, %2;" : "=l"(out) : "l"(a), "l"(b))
#define MUL2(out, a, b) asm("mul.rn.f32x2 %0, %1, %2;" : "=l"(out) : "l"(a), "l"(b))
#define FMA2(acc, a, b) asm("fma.rn.f32x2 %0, %1, %2, %0;" : "+l"(acc) : "l"(a), "l"(b))

__device__ __forceinline__ void warp_red(double& x) {
    #pragma unroll
    for (int o = 16; o > 0; o >>= 1) x += __shfl_down_sync(0xFFFFFFFFu, x, o);
}
__device__ __forceinline__ int buck_p(float p) {
    int b = (int)(p * 256.0f);
    return min(NB - 1, max(0, b));
}
__device__ __forceinline__ int buck_t(float t) {
    int b = (int)((t + 4.5f) * (256.0f / 9.0f));
    return min(NB - 1, max(0, b));
}

// ---------------------------------------------------------------------------
// K1: prep. wm, member lists (int atomics only), 7 per-block partials.
// ---------------------------------------------------------------------------
__global__ void k_prep(const float* __restrict__ p, const int* __restrict__ lab,
                       const float* __restrict__ t, const float* __restrict__ w, int n) {
    int tid = threadIdx.x;
    int idx = blockIdx.x * K1T + tid;

    int   y  = lab[idx];
    float wi = w[idx];
    float wm = (y == 0) ? wi : 0.0f;
    g_wm[idx] = wm;
    float pi = p[idx];
    float ti = t[idx];

    int bp = buck_p(pi);
    int sp_ = atomicAdd(&g_cntp[bp], 1);
    if (sp_ < CAP) g_mp[bp * CAP + sp_] = make_float2(pi, wm);

    int bt = buck_t(ti);
    int st_ = atomicAdd(&g_cntt[bt], 1);
    if (st_ < CAP) g_mt[bt * CAP + st_] = make_float2(ti, wm);

    float logp   = fmaxf(logf(pi),    -100.0f);
    float log1mp = fmaxf(log1pf(-pi), -100.0f);
    float loss   = (y != 0) ? -logp : -log1mp;

    double acc[7];
    acc[0] = (double)(wi * loss);
    acc[1] = (y == 0) ? 1.0 : 0.0;
    acc[2] = (double)wm;
    acc[3] = (double)wm * pi;
    acc[4] = (double)wm * pi * pi;
    acc[5] = (double)wm * ti;
    acc[6] = (double)wm * ti * ti;

    __shared__ double red[7][8];
    int lane = tid & 31, wid = tid >> 5;
    #pragma unroll
    for (int q = 0; q < 7; q++) warp_red(acc[q]);
    if (lane == 0) {
        #pragma unroll
        for (int q = 0; q < 7; q++) red[q][wid] = acc[q];
    }
    __syncthreads();
    if (tid == 0) {
        #pragma unroll
        for (int q = 0; q < 7; q++) {
            double s = 0;
            #pragma unroll
            for (int k = 0; k < K1T / 32; k++) s += red[q][k];
            g_part[q][blockIdx.x] = s;
        }
    }
}

// ---------------------------------------------------------------------------
// K2: exact u_i, v_i. 32 blocks x 256 threads. Bucket sums rebuilt from member
//     lists (one bucket per thread), scanned in shared, then per-element u,v
//     and Q-sum atomics.
// ---------------------------------------------------------------------------
__global__ void k_uv(const float* __restrict__ p, const float* __restrict__ t, int n) {
    int tid = threadIdx.x;
    __shared__ double sIWp[NB], sIXp[NB], sRWp[NB], sRXp[NB];
    __shared__ double sIWt[NB], sIXt[NB], sRWt[NB], sRXt[NB];

    // rebuild bucket sums from member lists (bucket tid)
    {
        int c = min(g_cntp[tid], CAP);
        const float2* m = &g_mp[tid * CAP];
        double Wb = 0, Xb = 0;
        #pragma unroll 4
        for (int k = 0; k < c; k++) {
            float2 e = m[k];
            Wb += (double)e.y;
            Xb += (double)e.y * (double)e.x;
        }
        sRWp[tid] = Wb; sIWp[tid] = Wb;
        sRXp[tid] = Xb; sIXp[tid] = Xb;
    }
    {
        int c = min(g_cntt[tid], CAP);
        const float2* m = &g_mt[tid * CAP];
        double Wb = 0, Xb = 0;
        #pragma unroll 4
        for (int k = 0; k < c; k++) {
            float2 e = m[k];
            Wb += (double)e.y;
            Xb += (double)e.y * (double)e.x;
        }
        sRWt[tid] = Wb; sIWt[tid] = Wb;
        sRXt[tid] = Xb; sIXt[tid] = Xb;
    }
    __syncthreads();

    // inclusive Hillis-Steele scan over 256 entries
    for (int off = 1; off < NB; off <<= 1) {
        double a = 0, b = 0, c = 0, d = 0;
        if (tid >= off) {
            a = sIWp[tid - off]; b = sIXp[tid - off];
            c = sIWt[tid - off]; d = sIXt[tid - off];
        }
        __syncthreads();
        sIWp[tid] += a; sIXp[tid] += b; sIWt[tid] += c; sIXt[tid] += d;
        __syncthreads();
    }

    int i = blockIdx.x * 256 + tid;
    float pi  = p[i];
    float ti  = t[i];
    float wmi = g_wm[i];

    double Wtp = sIWp[NB - 1], Xtp = sIXp[NB - 1];
    double Wtt = sIWt[NB - 1], Xtt = sIXt[NB - 1];

    double u;
    {
        int b = buck_p(pi);
        double Wlo = sIWp[b] - sRWp[b];
        double Xlo = sIXp[b] - sRXp[b];
        double Whi = Wtp - sIWp[b];
        double Xhi = Xtp - sIXp[b];
        u = (double)pi * (Wlo - Whi) - Xlo + Xhi;
        int c = min(g_cntp[b], CAP);
        const float2* m = &g_mp[b * CAP];
        float s = 0.0f;
        #pragma unroll 4
        for (int k = 0; k < c; k++) {
            float2 e = m[k];
            s = fmaf(e.y, fabsf(pi - e.x), s);
        }
        u += (double)s;
    }
    double v;
    {
        int b = buck_t(ti);
        double Wlo = sIWt[b] - sRWt[b];
        double Xlo = sIXt[b] - sRXt[b];
        double Whi = Wtt - sIWt[b];
        double Xhi = Xtt - sIXt[b];
        v = (double)ti * (Wlo - Whi) - Xlo + Xhi;
        int c = min(g_cntt[b], CAP);
        const float2* m = &g_mt[b * CAP];
        float s = 0.0f;
        #pragma unroll 4
        for (int k = 0; k < c; k++) {
            float2 e = m[k];
            s = fmaf(e.y, fabsf(ti - e.x), s);
        }
        v += (double)s;
    }

    double acc[5];
    acc[0] = (double)wmi * u;
    acc[1] = (double)wmi * v;
    acc[2] = (double)wmi * u * v;
    acc[3] = (double)wmi * u * u;
    acc[4] = (double)wmi * v * v;

    __shared__ double red[5][8];
    int lane = tid & 31, wid = tid >> 5;
    #pragma unroll
    for (int q = 0; q < 5; q++) warp_red(acc[q]);
    if (lane == 0) {
        #pragma unroll
        for (int q = 0; q < 5; q++) red[q][wid] = acc[q];
    }
    __syncthreads();
    if (tid == 0) {
        #pragma unroll
        for (int q = 0; q < 5; q++) {
            double s = 0;
            #pragma unroll
            for (int k = 0; k < 8; k++) s += red[q][k];
            atomicAdd(&g_S[q], s);
        }
    }
}

// ---------------------------------------------------------------------------
// K3: N^2 pass (P_ab only) + last-block finalize. Slim smem (R5 shape).
// ---------------------------------------------------------------------------
__global__ void k_pab(const float* __restrict__ p, const float* __restrict__ t,
                      float* __restrict__ out, int n) {
    int tid = threadIdx.x;
    int i0  = blockIdx.x * (TB4 * ROWS) + tid * ROWS;
    int j0  = blockIdx.y * TB4;

    float4 pv = *(const float4*)(p + i0);
    float4 tv = *(const float4*)(t + i0);
    ull pA0 = pack2(pv.x, pv.y), pA1 = pack2(pv.z, pv.w);
    ull tA0 = pack2(tv.x, tv.y), tA1 = pack2(tv.z, tv.w);

    __shared__ ulonglong2 sPT[TB4];  // {-pj dup, -tj dup}
    __shared__ ull        sW[TB4];   // {wm_j dup}
    {
        int j = j0 + tid;
        float pj = p[j], tj = t[j], wj = g_wm[j];
        sPT[tid] = make_ulonglong2(pack2(-pj, -pj), pack2(-tj, -tj));
        sW[tid]  = pack2(wj, wj);
    }
    __syncthreads();

    ull ab0 = 0, ab1 = 0;
    #pragma unroll 8
    for (int k = 0; k < TB4; k++) {
        ulonglong2 pt = sPT[k];
        ull wk = sW[k];
        ull dA, dB, m;
        ADD2(dA, pA0, pt.x);
        ADD2(dB, tA0, pt.y);
        MUL2(m, dA, dB); m &= ABSMASK;   // |dp*dt| == |dp||dt|
        FMA2(ab0, m, wk);
        ADD2(dA, pA1, pt.x);
        ADD2(dB, tA1, pt.y);
        MUL2(m, dA, dB); m &= ABSMASK;
        FMA2(ab1, m, wk);
    }

    double w0 = (double)g_wm[i0 + 0], w1 = (double)g_wm[i0 + 1];
    double w2 = (double)g_wm[i0 + 2], w3 = (double)g_wm[i0 + 3];
    double dAB = w0 * lo2(ab0) + w1 * hi2(ab0) + w2 * lo2(ab1) + w3 * hi2(ab1);

    __shared__ double red[4];
    int lane = tid & 31, wid = tid >> 5;
    warp_red(dAB);
    if (lane == 0) red[wid] = dAB;
    __syncthreads();

    __shared__ bool amLast;
    if (tid == 0) {
        atomicAdd(&g_Pab, red[0] + red[1] + red[2] + red[3]);
        __threadfence();
        unsigned vtk = atomicAdd(&g_ticket, 1u);
        amLast = (vtk == (unsigned)(NBLK - 1));
    }
    __syncthreads();
    if (!amLast) return;

    // ---- finalize ----
    __shared__ double pr[7];
    if (tid < 7) {
        double s = 0;
        #pragma unroll
        for (int k = 0; k < K1B; k++) s += g_part[tid][k];
        pr[tid] = s;
    }
    __syncthreads();
    if (tid == 0) {
        double bce_s = pr[0], nf = pr[1], W = pr[2];
        double Sp = pr[3], Sp2 = pr[4], St = pr[5], St2 = pr[6];

        double Paa = 2.0 * (W * Sp2 - Sp * Sp);
        double Pbb = 2.0 * (W * St2 - St * St);
        double sa = g_S[0], sb = g_S[1], qab = g_S[2], qaa = g_S[3], qbb = g_S[4];

        double inv2 = 1.0 / (nf * nf);
        double at = sa * inv2;
        double bt = sb * inv2;
        double cQ = (2.0 * W - 4.0 * nf) * inv2;
        double cT = 4.0 * nf * nf - 4.0 * W * nf + W * W;

        double SAB = g_Pab + cQ * qab + at * bt * cT;
        double SAA = Paa   + cQ * qaa + at * at * cT;
        double SBB = Pbb   + cQ * qbb + bt * bt * cT;

        double bce   = bce_s / (double)n;
        double dcorr = (SAB * SAB) / (SAA * SBB);
        double ld    = DISCO_LAMBDA * dcorr;
        out[0] = (float)(bce + ld);
        out[1] = (float)bce;
        out[2] = (float)ld;
    }
    // re-zero scratch for next graph replay
    for (int b = tid; b < NB; b += TB4) { g_cntp[b] = 0; g_cntt[b] = 0; }
    if (tid < 5) g_S[tid] = 0.0;
    if (tid == 0) { g_Pab = 0.0; g_ticket = 0u; }
}

// ---------------------------------------------------------------------------
extern "C" void kernel_launch(void* const* d_in, const int* in_sizes, int n_in,
                              void* d_out, int out_size) {
    const float* p   = (const float*)d_in[0];  // inferences
    const int*   lab = (const int*)  d_in[1];  // labels
    const float* t   = (const float*)d_in[2];  // disco_target
    const float* w   = (const float*)d_in[3];  // weights
    float* out = (float*)d_out;
    int n = in_sizes[0];

    k_prep<<<K1B, K1T>>>(p, lab, t, w, n);
    k_uv<<<n / 256, 256>>>(p, t, n);
    dim3 grid(GX, GY);   // 16 x 64 = 1024 blocks of 128
    k_pab<<<grid, TB4>>>(p, t, out, n);
}

// round 8
// speedup vs baseline: 1.5598x; 1.5598x over previous
#include <cuda_runtime.h>

// SingleDisCoLoss: BCE + 0.1 * weighted dcorr^2 over labels==0 subset. N=8192.
// Round 8: exact R5 structure (best: 56.1us) + single change: k_pab ROWS 4->8.
//   P_aa, P_bb: closed form O(N).
//   u_i, v_i:   exact via monotone 256-bucket prefix sums + in-bucket pairs.
//   S_XY = P_xy + (2W-4nf)/nf^2 * Q_xy + xt*yt*(4nf^2-4W nf+W^2)

#define MAXN 8192
#define NB   256        // buckets
#define CAP  256        // bucket member capacity
#define TB4  128
#define ROWS 8
#define GY   64
#define GX   (MAXN / (TB4 * ROWS))          // 8
#define NBLK (GX * GY)                      // 512
#define K1B  32
#define K1T  256
#define DISCO_LAMBDA 0.1
#define ABSMASK 0x7FFFFFFF7FFFFFFFULL

typedef unsigned long long ull;

// ---- scratch (device globals; zero at load; re-zeroed by finalize path) ----
__device__ float  g_wm[MAXN];
__device__ double g_Wbp[NB], g_Xbp[NB], g_Wbt[NB], g_Xbt[NB];
__device__ int    g_cntp[NB], g_cntt[NB];
__device__ float2 g_mp[NB * CAP], g_mt[NB * CAP];   // {value, wm}
__device__ double g_part[7][K1B];   // bce, nf, W, Sp, Sp2, St, St2
__device__ double g_S[5];           // sa, sb, qab, qaa, qbb (atomic)
__device__ double g_Pab;            // atomic
__device__ unsigned g_ticket;

// ---- helpers --------------------------------------------------------------
__device__ __forceinline__ ull pack2(float a, float b) {
    ull r; asm("mov.b64 %0, {%1, %2};" : "=l"(r) : "f"(a), "f"(b)); return r;
}
__device__ __forceinline__ float lo2(ull x) { return __uint_as_float((unsigned)x); }
__device__ __forceinline__ float hi2(ull x) { return __uint_as_float((unsigned)(x >> 32)); }
#define ADD2(out, a, b) asm("add.rn.f32x2 %0, %1, %2;" : "=l"(out) : "l"(a), "l"(b))
#define MUL2(out, a, b) asm("mul.rn.f32x2 %0, %1, %2;" : "=l"(out) : "l"(a), "l"(b))
#define FMA2(acc, a, b) asm("fma.rn.f32x2 %0, %1, %2, %0;" : "+l"(acc) : "l"(a), "l"(b))

__device__ __forceinline__ void warp_red(double& x) {
    #pragma unroll
    for (int o = 16; o > 0; o >>= 1) x += __shfl_down_sync(0xFFFFFFFFu, x, o);
}
__device__ __forceinline__ int buck_p(float p) {
    int b = (int)(p * 256.0f);
    return min(NB - 1, max(0, b));
}
__device__ __forceinline__ int buck_t(float t) {
    int b = (int)((t + 4.5f) * (256.0f / 9.0f));
    return min(NB - 1, max(0, b));
}

// ---------------------------------------------------------------------------
// K1: prep (R5 version). wm, bucket hists (shared-first), member lists,
//     7 per-block partials.
// ---------------------------------------------------------------------------
__global__ void k_prep(const float* __restrict__ p, const int* __restrict__ lab,
                       const float* __restrict__ t, const float* __restrict__ w, int n) {
    int tid = threadIdx.x;
    int idx = blockIdx.x * K1T + tid;

    __shared__ double hWp[NB], hXp[NB], hWt[NB], hXt[NB];
    hWp[tid] = 0.0; hXp[tid] = 0.0; hWt[tid] = 0.0; hXt[tid] = 0.0;
    __syncthreads();

    double acc[7] = {0, 0, 0, 0, 0, 0, 0};
    {
        int   y  = lab[idx];
        float wi = w[idx];
        float wm = (y == 0) ? wi : 0.0f;
        g_wm[idx] = wm;
        float pi = p[idx];
        float ti = t[idx];

        int bp = buck_p(pi);
        atomicAdd(&hWp[bp], (double)wm);
        atomicAdd(&hXp[bp], (double)wm * (double)pi);
        int sp_ = atomicAdd(&g_cntp[bp], 1);
        if (sp_ < CAP) g_mp[bp * CAP + sp_] = make_float2(pi, wm);

        int bt = buck_t(ti);
        atomicAdd(&hWt[bt], (double)wm);
        atomicAdd(&hXt[bt], (double)wm * (double)ti);
        int st_ = atomicAdd(&g_cntt[bt], 1);
        if (st_ < CAP) g_mt[bt * CAP + st_] = make_float2(ti, wm);

        float logp   = fmaxf(logf(pi),    -100.0f);
        float log1mp = fmaxf(log1pf(-pi), -100.0f);
        float loss   = (y != 0) ? -logp : -log1mp;
        acc[0] = (double)(wi * loss);
        acc[1] = (y == 0) ? 1.0 : 0.0;
        acc[2] = (double)wm;
        acc[3] = (double)wm * pi;
        acc[4] = (double)wm * pi * pi;
        acc[5] = (double)wm * ti;
        acc[6] = (double)wm * ti * ti;
    }
    __syncthreads();
    // flush shared buckets: one global atomic per bucket per block (if nonzero)
    if (hWp[tid] != 0.0) { atomicAdd(&g_Wbp[tid], hWp[tid]); atomicAdd(&g_Xbp[tid], hXp[tid]); }
    if (hWt[tid] != 0.0) { atomicAdd(&g_Wbt[tid], hWt[tid]); atomicAdd(&g_Xbt[tid], hXt[tid]); }

    __shared__ double red[7][8];
    int lane = tid & 31, wid = tid >> 5;
    #pragma unroll
    for (int q = 0; q < 7; q++) warp_red(acc[q]);
    if (lane == 0) {
        #pragma unroll
        for (int q = 0; q < 7; q++) red[q][wid] = acc[q];
    }
    __syncthreads();
    if (tid == 0) {
        #pragma unroll
        for (int q = 0; q < 7; q++) {
            double s = 0;
            #pragma unroll
            for (int k = 0; k < K1T / 32; k++) s += red[q][k];
            g_part[q][blockIdx.x] = s;
        }
    }
}

// ---------------------------------------------------------------------------
// K2: exact u_i, v_i via bucket prefix sums; accumulate Q sums (atomic g_S).
//     (R5 version: reads g_Wbp/g_Xbp/... built by k_prep.)
// ---------------------------------------------------------------------------
__global__ void k_uv(const float* __restrict__ p, const float* __restrict__ t, int n) {
    int tid = threadIdx.x;
    __shared__ double sIWp[NB], sIXp[NB], sRWp[NB], sRXp[NB];
    __shared__ double sIWt[NB], sIXt[NB], sRWt[NB], sRXt[NB];
    {
        double a = g_Wbp[tid], b = g_Xbp[tid], c = g_Wbt[tid], d = g_Xbt[tid];
        sRWp[tid] = a; sIWp[tid] = a;
        sRXp[tid] = b; sIXp[tid] = b;
        sRWt[tid] = c; sIWt[tid] = c;
        sRXt[tid] = d; sIXt[tid] = d;
    }
    __syncthreads();
    for (int off = 1; off < NB; off <<= 1) {
        double a = 0, b = 0, c = 0, d = 0;
        if (tid >= off) {
            a = sIWp[tid - off]; b = sIXp[tid - off];
            c = sIWt[tid - off]; d = sIXt[tid - off];
        }
        __syncthreads();
        sIWp[tid] += a; sIXp[tid] += b; sIWt[tid] += c; sIXt[tid] += d;
        __syncthreads();
    }

    int i = blockIdx.x * 256 + tid;
    float pi  = p[i];
    float ti  = t[i];
    float wmi = g_wm[i];

    double Wtp = sIWp[NB - 1], Xtp = sIXp[NB - 1];
    double Wtt = sIWt[NB - 1], Xtt = sIXt[NB - 1];

    double u;
    {
        int b = buck_p(pi);
        double Wlo = sIWp[b] - sRWp[b];
        double Xlo = sIXp[b] - sRXp[b];
        double Whi = Wtp - sIWp[b];
        double Xhi = Xtp - sIXp[b];
        u = (double)pi * (Wlo - Whi) - Xlo + Xhi;
        int c = min(g_cntp[b], CAP);
        const float2* m = &g_mp[b * CAP];
        float s = 0.0f;
        #pragma unroll 4
        for (int k = 0; k < c; k++) {
            float2 e = m[k];
            s = fmaf(e.y, fabsf(pi - e.x), s);
        }
        u += (double)s;
    }
    double v;
    {
        int b = buck_t(ti);
        double Wlo = sIWt[b] - sRWt[b];
        double Xlo = sIXt[b] - sRXt[b];
        double Whi = Wtt - sIWt[b];
        double Xhi = Xtt - sIXt[b];
        v = (double)ti * (Wlo - Whi) - Xlo + Xhi;
        int c = min(g_cntt[b], CAP);
        const float2* m = &g_mt[b * CAP];
        float s = 0.0f;
        #pragma unroll 4
        for (int k = 0; k < c; k++) {
            float2 e = m[k];
            s = fmaf(e.y, fabsf(ti - e.x), s);
        }
        v += (double)s;
    }

    double acc[5];
    acc[0] = (double)wmi * u;
    acc[1] = (double)wmi * v;
    acc[2] = (double)wmi * u * v;
    acc[3] = (double)wmi * u * u;
    acc[4] = (double)wmi * v * v;

    __shared__ double red[5][8];
    int lane = tid & 31, wid = tid >> 5;
    #pragma unroll
    for (int q = 0; q < 5; q++) warp_red(acc[q]);
    if (lane == 0) {
        #pragma unroll
        for (int q = 0; q < 5; q++) red[q][wid] = acc[q];
    }
    __syncthreads();
    if (tid == 0) {
        #pragma unroll
        for (int q = 0; q < 5; q++) {
            double s = 0;
            #pragma unroll
            for (int k = 0; k < 8; k++) s += red[q][k];
            atomicAdd(&g_S[q], s);
        }
    }
}

// ---------------------------------------------------------------------------
// K3: N^2 pass (P_ab only), ROWS=8 per thread + last-block finalize.
// ---------------------------------------------------------------------------
__global__ void k_pab(const float* __restrict__ p, const float* __restrict__ t,
                      float* __restrict__ out, int n) {
    int tid = threadIdx.x;
    int i0  = blockIdx.x * (TB4 * ROWS) + tid * ROWS;
    int j0  = blockIdx.y * TB4;

    float4 pv0 = *(const float4*)(p + i0);
    float4 pv1 = *(const float4*)(p + i0 + 4);
    float4 tv0 = *(const float4*)(t + i0);
    float4 tv1 = *(const float4*)(t + i0 + 4);
    ull pA0 = pack2(pv0.x, pv0.y), pA1 = pack2(pv0.z, pv0.w);
    ull pA2 = pack2(pv1.x, pv1.y), pA3 = pack2(pv1.z, pv1.w);
    ull tA0 = pack2(tv0.x, tv0.y), tA1 = pack2(tv0.z, tv0.w);
    ull tA2 = pack2(tv1.x, tv1.y), tA3 = pack2(tv1.z, tv1.w);

    __shared__ ulonglong2 sPT[TB4];  // {-pj dup, -tj dup}
    __shared__ ull        sW[TB4];   // {wm_j dup}
    {
        int j = j0 + tid;
        float pj = p[j], tj = t[j], wj = g_wm[j];
        sPT[tid] = make_ulonglong2(pack2(-pj, -pj), pack2(-tj, -tj));
        sW[tid]  = pack2(wj, wj);
    }
    __syncthreads();

    ull ab0 = 0, ab1 = 0, ab2 = 0, ab3 = 0;
    #pragma unroll 4
    for (int k = 0; k < TB4; k++) {
        ulonglong2 pt = sPT[k];
        ull wk = sW[k];
        ull dA, dB, m;
        ADD2(dA, pA0, pt.x);
        ADD2(dB, tA0, pt.y);
        MUL2(m, dA, dB); m &= ABSMASK;   // |dp*dt| == |dp||dt|
        FMA2(ab0, m, wk);
        ADD2(dA, pA1, pt.x);
        ADD2(dB, tA1, pt.y);
        MUL2(m, dA, dB); m &= ABSMASK;
        FMA2(ab1, m, wk);
        ADD2(dA, pA2, pt.x);
        ADD2(dB, tA2, pt.y);
        MUL2(m, dA, dB); m &= ABSMASK;
        FMA2(ab2, m, wk);
        ADD2(dA, pA3, pt.x);
        ADD2(dB, tA3, pt.y);
        MUL2(m, dA, dB); m &= ABSMASK;
        FMA2(ab3, m, wk);
    }

    double dAB =
        (double)g_wm[i0 + 0] * lo2(ab0) + (double)g_wm[i0 + 1] * hi2(ab0) +
        (double)g_wm[i0 + 2] * lo2(ab1) + (double)g_wm[i0 + 3] * hi2(ab1) +
        (double)g_wm[i0 + 4] * lo2(ab2) + (double)g_wm[i0 + 5] * hi2(ab2) +
        (double)g_wm[i0 + 6] * lo2(ab3) + (double)g_wm[i0 + 7] * hi2(ab3);

    __shared__ double red[4];
    int lane = tid & 31, wid = tid >> 5;
    warp_red(dAB);
    if (lane == 0) red[wid] = dAB;
    __syncthreads();

    __shared__ bool amLast;
    if (tid == 0) {
        atomicAdd(&g_Pab, red[0] + red[1] + red[2] + red[3]);
        __threadfence();
        unsigned vtk = atomicAdd(&g_ticket, 1u);
        amLast = (vtk == (unsigned)(NBLK - 1));
    }
    __syncthreads();
    if (!amLast) return;

    // ---- finalize (parallel) ----
    __shared__ double pr[7];
    if (tid < 7) {
        double s = 0;
        #pragma unroll
        for (int k = 0; k < K1B; k++) s += g_part[tid][k];
        pr[tid] = s;
    }
    __syncthreads();
    if (tid == 0) {
        double bce_s = pr[0], nf = pr[1], W = pr[2];
        double Sp = pr[3], Sp2 = pr[4], St = pr[5], St2 = pr[6];

        double Paa = 2.0 * (W * Sp2 - Sp * Sp);
        double Pbb = 2.0 * (W * St2 - St * St);
        double sa = g_S[0], sb = g_S[1], qab = g_S[2], qaa = g_S[3], qbb = g_S[4];

        double inv2 = 1.0 / (nf * nf);
        double at = sa * inv2;
        double bt = sb * inv2;
        double cQ = (2.0 * W - 4.0 * nf) * inv2;
        double cT = 4.0 * nf * nf - 4.0 * W * nf + W * W;

        double SAB = g_Pab + cQ * qab + at * bt * cT;
        double SAA = Paa   + cQ * qaa + at * at * cT;
        double SBB = Pbb   + cQ * qbb + bt * bt * cT;

        double bce   = bce_s / (double)n;
        double dcorr = (SAB * SAB) / (SAA * SBB);
        double ld    = DISCO_LAMBDA * dcorr;
        out[0] = (float)(bce + ld);
        out[1] = (float)bce;
        out[2] = (float)ld;
    }
    // re-zero scratch for next graph replay
    for (int b = tid; b < NB; b += TB4) {
        g_Wbp[b] = 0.0; g_Xbp[b] = 0.0;
        g_Wbt[b] = 0.0; g_Xbt[b] = 0.0;
        g_cntp[b] = 0;  g_cntt[b] = 0;
    }
    if (tid < 5) g_S[tid] = 0.0;
    if (tid == 0) { g_Pab = 0.0; g_ticket = 0u; }
}

// ---------------------------------------------------------------------------
extern "C" void kernel_launch(void* const* d_in, const int* in_sizes, int n_in,
                              void* d_out, int out_size) {
    const float* p   = (const float*)d_in[0];  // inferences
    const int*   lab = (const int*)  d_in[1];  // labels
    const float* t   = (const float*)d_in[2];  // disco_target
    const float* w   = (const float*)d_in[3];  // weights
    float* out = (float*)d_out;
    int n = in_sizes[0];

    k_prep<<<K1B, K1T>>>(p, lab, t, w, n);
    k_uv<<<n / 256, 256>>>(p, t, n);
    dim3 grid(GX, GY);   // 8 x 64 = 512 blocks of 128
    k_pab<<<grid, TB4>>>(p, t, out, n);
}

// round 9
// speedup vs baseline: 1.5780x; 1.0117x over previous
#include <cuda_runtime.h>

// SingleDisCoLoss: BCE + 0.1 * weighted dcorr^2 over labels==0 subset. N=8192.
// Round 9: R5 config (best measured) with k_prep+k_uv fused into one kernel
//          via an internal spin barrier (32 blocks, all resident). 2 launches.
//   P_aa, P_bb: closed form O(N).
//   u_i, v_i:   exact via monotone 256-bucket prefix sums + in-bucket pairs.
//   S_XY = P_xy + (2W-4nf)/nf^2 * Q_xy + xt*yt*(4nf^2-4W nf+W^2)

#define MAXN 8192
#define NB   256        // buckets
#define CAP  256        // bucket member capacity
#define TB4  128
#define ROWS 4
#define GY   64
#define GX   (MAXN / (TB4 * ROWS))          // 16
#define NBLK (GX * GY)                      // 1024
#define K1B  32
#define K1T  256
#define DISCO_LAMBDA 0.1
#define ABSMASK 0x7FFFFFFF7FFFFFFFULL

typedef unsigned long long ull;

// ---- scratch (device globals; zero at load; re-zeroed by finalize path) ----
__device__ float  g_wm[MAXN];
__device__ double g_Wbp[NB], g_Xbp[NB], g_Wbt[NB], g_Xbt[NB];
__device__ int    g_cntp[NB], g_cntt[NB];
__device__ float2 g_mp[NB * CAP], g_mt[NB * CAP];   // {value, wm}
__device__ double g_part[7][K1B];   // bce, nf, W, Sp, Sp2, St, St2
__device__ double g_S[5];           // sa, sb, qab, qaa, qbb (atomic)
__device__ double g_Pab;            // atomic
__device__ unsigned g_ticket;
__device__ volatile unsigned g_sync;

// ---- helpers --------------------------------------------------------------
__device__ __forceinline__ ull pack2(float a, float b) {
    ull r; asm("mov.b64 %0, {%1, %2};" : "=l"(r) : "f"(a), "f"(b)); return r;
}
__device__ __forceinline__ float lo2(ull x) { return __uint_as_float((unsigned)x); }
__device__ __forceinline__ float hi2(ull x) { return __uint_as_float((unsigned)(x >> 32)); }
#define ADD2(out, a, b) asm("add.rn.f32x2 %0, %1, %2;" : "=l"(out) : "l"(a), "l"(b))
#define MUL2(out, a, b) asm("mul.rn.f32x2 %0, %1, %2;" : "=l"(out) : "l"(a), "l"(b))
#define FMA2(acc, a, b) asm("fma.rn.f32x2 %0, %1, %2, %0;" : "+l"(acc) : "l"(a), "l"(b))

__device__ __forceinline__ void warp_red(double& x) {
    #pragma unroll
    for (int o = 16; o > 0; o >>= 1) x += __shfl_down_sync(0xFFFFFFFFu, x, o);
}
__device__ __forceinline__ int buck_p(float p) {
    int b = (int)(p * 256.0f);
    return min(NB - 1, max(0, b));
}
__device__ __forceinline__ int buck_t(float t) {
    int b = (int)((t + 4.5f) * (256.0f / 9.0f));
    return min(NB - 1, max(0, b));
}

// ---------------------------------------------------------------------------
// K1: fused prep + uv. 32 blocks x 256 threads (all resident -> spin barrier OK).
// Phase 1 (== R5 k_prep): wm, bucket hists (shared-first), member lists,
//                         7 per-block partials.
// Spin barrier on g_sync.
// Phase 2 (== R5 k_uv):   bucket prefix scan, exact u/v, Q-sum atomics.
// ---------------------------------------------------------------------------
__global__ void k_prep_uv(const float* __restrict__ p, const int* __restrict__ lab,
                          const float* __restrict__ t, const float* __restrict__ w, int n) {
    int tid = threadIdx.x;
    int idx = blockIdx.x * K1T + tid;

    // 8 x 256 doubles, reused across phases (16 KB)
    __shared__ double sA[NB], sB[NB], sC[NB], sD[NB];
    __shared__ double sE[NB], sF[NB], sG[NB], sH[NB];

    // ---------------- phase 1: prep ----------------
    // hists in sA..sD
    sA[tid] = 0.0; sB[tid] = 0.0; sC[tid] = 0.0; sD[tid] = 0.0;
    __syncthreads();

    float pi = p[idx];
    float ti = t[idx];
    double acc[7];
    {
        int   y  = lab[idx];
        float wi = w[idx];
        float wm = (y == 0) ? wi : 0.0f;
        g_wm[idx] = wm;

        int bp = buck_p(pi);
        atomicAdd(&sA[bp], (double)wm);
        atomicAdd(&sB[bp], (double)wm * (double)pi);
        int sp_ = atomicAdd(&g_cntp[bp], 1);
        if (sp_ < CAP) g_mp[bp * CAP + sp_] = make_float2(pi, wm);

        int bt = buck_t(ti);
        atomicAdd(&sC[bt], (double)wm);
        atomicAdd(&sD[bt], (double)wm * (double)ti);
        int st_ = atomicAdd(&g_cntt[bt], 1);
        if (st_ < CAP) g_mt[bt * CAP + st_] = make_float2(ti, wm);

        float logp   = fmaxf(logf(pi),    -100.0f);
        float log1mp = fmaxf(log1pf(-pi), -100.0f);
        float loss   = (y != 0) ? -logp : -log1mp;
        acc[0] = (double)(wi * loss);
        acc[1] = (y == 0) ? 1.0 : 0.0;
        acc[2] = (double)wm;
        acc[3] = (double)wm * pi;
        acc[4] = (double)wm * pi * pi;
        acc[5] = (double)wm * ti;
        acc[6] = (double)wm * ti * ti;
    }
    __syncthreads();
    // flush shared hists to global
    if (sA[tid] != 0.0) { atomicAdd(&g_Wbp[tid], sA[tid]); atomicAdd(&g_Xbp[tid], sB[tid]); }
    if (sC[tid] != 0.0) { atomicAdd(&g_Wbt[tid], sC[tid]); atomicAdd(&g_Xbt[tid], sD[tid]); }

    {
        __shared__ double red7[7][8];
        int lane = tid & 31, wid = tid >> 5;
        #pragma unroll
        for (int q = 0; q < 7; q++) warp_red(acc[q]);
        if (lane == 0) {
            #pragma unroll
            for (int q = 0; q < 7; q++) red7[q][wid] = acc[q];
        }
        __syncthreads();
        if (tid == 0) {
            #pragma unroll
            for (int q = 0; q < 7; q++) {
                double s = 0;
                #pragma unroll
                for (int k = 0; k < K1T / 32; k++) s += red7[q][k];
                g_part[q][blockIdx.x] = s;
            }
        }
    }

    // ---------------- spin barrier across 32 blocks ----------------
    __syncthreads();
    if (tid == 0) {
        __threadfence();
        atomicAdd((unsigned*)&g_sync, 1u);
        while (g_sync < (unsigned)K1B) { }
        __threadfence();
    }
    __syncthreads();

    // ---------------- phase 2: uv ----------------
    // sA..sD = inclusive scans; sE..sH = raw per-bucket values
    {
        double a = g_Wbp[tid], b = g_Xbp[tid], c = g_Wbt[tid], d = g_Xbt[tid];
        sE[tid] = a; sA[tid] = a;
        sF[tid] = b; sB[tid] = b;
        sG[tid] = c; sC[tid] = c;
        sH[tid] = d; sD[tid] = d;
    }
    __syncthreads();
    for (int off = 1; off < NB; off <<= 1) {
        double a = 0, b = 0, c = 0, d = 0;
        if (tid >= off) {
            a = sA[tid - off]; b = sB[tid - off];
            c = sC[tid - off]; d = sD[tid - off];
        }
        __syncthreads();
        sA[tid] += a; sB[tid] += b; sC[tid] += c; sD[tid] += d;
        __syncthreads();
    }

    float wmi = g_wm[idx];
    double Wtp = sA[NB - 1], Xtp = sB[NB - 1];
    double Wtt = sC[NB - 1], Xtt = sD[NB - 1];

    double u;
    {
        int b = buck_p(pi);
        double Wlo = sA[b] - sE[b];
        double Xlo = sB[b] - sF[b];
        double Whi = Wtp - sA[b];
        double Xhi = Xtp - sB[b];
        u = (double)pi * (Wlo - Whi) - Xlo + Xhi;
        int c = min(g_cntp[b], CAP);
        const float2* m = &g_mp[b * CAP];
        float s = 0.0f;
        #pragma unroll 4
        for (int k = 0; k < c; k++) {
            float2 e = m[k];
            s = fmaf(e.y, fabsf(pi - e.x), s);
        }
        u += (double)s;
    }
    double v;
    {
        int b = buck_t(ti);
        double Wlo = sC[b] - sG[b];
        double Xlo = sD[b] - sH[b];
        double Whi = Wtt - sC[b];
        double Xhi = Xtt - sD[b];
        v = (double)ti * (Wlo - Whi) - Xlo + Xhi;
        int c = min(g_cntt[b], CAP);
        const float2* m = &g_mt[b * CAP];
        float s = 0.0f;
        #pragma unroll 4
        for (int k = 0; k < c; k++) {
            float2 e = m[k];
            s = fmaf(e.y, fabsf(ti - e.x), s);
        }
        v += (double)s;
    }

    double acc5[5];
    acc5[0] = (double)wmi * u;
    acc5[1] = (double)wmi * v;
    acc5[2] = (double)wmi * u * v;
    acc5[3] = (double)wmi * u * u;
    acc5[4] = (double)wmi * v * v;

    __shared__ double red5[5][8];
    int lane = tid & 31, wid = tid >> 5;
    #pragma unroll
    for (int q = 0; q < 5; q++) warp_red(acc5[q]);
    if (lane == 0) {
        #pragma unroll
        for (int q = 0; q < 5; q++) red5[q][wid] = acc5[q];
    }
    __syncthreads();
    if (tid == 0) {
        #pragma unroll
        for (int q = 0; q < 5; q++) {
            double s = 0;
            #pragma unroll
            for (int k = 0; k < 8; k++) s += red5[q][k];
            atomicAdd(&g_S[q], s);
        }
    }
}

// ---------------------------------------------------------------------------
// K2: N^2 pass (P_ab only, R5 ROWS=4 version) + last-block finalize.
// ---------------------------------------------------------------------------
__global__ void k_pab(const float* __restrict__ p, const float* __restrict__ t,
                      float* __restrict__ out, int n) {
    int tid = threadIdx.x;
    int i0  = blockIdx.x * (TB4 * ROWS) + tid * ROWS;
    int j0  = blockIdx.y * TB4;

    float4 pv = *(const float4*)(p + i0);
    float4 tv = *(const float4*)(t + i0);
    ull pA0 = pack2(pv.x, pv.y), pA1 = pack2(pv.z, pv.w);
    ull tA0 = pack2(tv.x, tv.y), tA1 = pack2(tv.z, tv.w);

    __shared__ ulonglong2 sPT[TB4];  // {-pj dup, -tj dup}
    __shared__ ull        sW[TB4];   // {wm_j dup}
    {
        int j = j0 + tid;
        float pj = p[j], tj = t[j], wj = g_wm[j];
        sPT[tid] = make_ulonglong2(pack2(-pj, -pj), pack2(-tj, -tj));
        sW[tid]  = pack2(wj, wj);
    }
    __syncthreads();

    ull ab0 = 0, ab1 = 0;
    #pragma unroll 8
    for (int k = 0; k < TB4; k++) {
        ulonglong2 pt = sPT[k];
        ull wk = sW[k];
        ull dA, dB, m;
        ADD2(dA, pA0, pt.x);
        ADD2(dB, tA0, pt.y);
        MUL2(m, dA, dB); m &= ABSMASK;   // |dp*dt| == |dp||dt|
        FMA2(ab0, m, wk);
        ADD2(dA, pA1, pt.x);
        ADD2(dB, tA1, pt.y);
        MUL2(m, dA, dB); m &= ABSMASK;
        FMA2(ab1, m, wk);
    }

    double w0 = (double)g_wm[i0 + 0], w1 = (double)g_wm[i0 + 1];
    double w2 = (double)g_wm[i0 + 2], w3 = (double)g_wm[i0 + 3];
    double dAB = w0 * lo2(ab0) + w1 * hi2(ab0) + w2 * lo2(ab1) + w3 * hi2(ab1);

    __shared__ double red[4];
    int lane = tid & 31, wid = tid >> 5;
    warp_red(dAB);
    if (lane == 0) red[wid] = dAB;
    __syncthreads();

    __shared__ bool amLast;
    if (tid == 0) {
        atomicAdd(&g_Pab, red[0] + red[1] + red[2] + red[3]);
        __threadfence();
        unsigned vtk = atomicAdd(&g_ticket, 1u);
        amLast = (vtk == (unsigned)(NBLK - 1));
    }
    __syncthreads();
    if (!amLast) return;

    // ---- finalize ----
    __shared__ double pr[7];
    if (tid < 7) {
        double s = 0;
        #pragma unroll
        for (int k = 0; k < K1B; k++) s += g_part[tid][k];
        pr[tid] = s;
    }
    __syncthreads();
    if (tid == 0) {
        double bce_s = pr[0], nf = pr[1], W = pr[2];
        double Sp = pr[3], Sp2 = pr[4], St = pr[5], St2 = pr[6];

        double Paa = 2.0 * (W * Sp2 - Sp * Sp);
        double Pbb = 2.0 * (W * St2 - St * St);
        double sa = g_S[0], sb = g_S[1], qab = g_S[2], qaa = g_S[3], qbb = g_S[4];

        double inv2 = 1.0 / (nf * nf);
        double at = sa * inv2;
        double bt = sb * inv2;
        double cQ = (2.0 * W - 4.0 * nf) * inv2;
        double cT = 4.0 * nf * nf - 4.0 * W * nf + W * W;

        double SAB = g_Pab + cQ * qab + at * bt * cT;
        double SAA = Paa   + cQ * qaa + at * at * cT;
        double SBB = Pbb   + cQ * qbb + bt * bt * cT;

        double bce   = bce_s / (double)n;
        double dcorr = (SAB * SAB) / (SAA * SBB);
        double ld    = DISCO_LAMBDA * dcorr;
        out[0] = (float)(bce + ld);
        out[1] = (float)bce;
        out[2] = (float)ld;
    }
    // re-zero scratch for next graph replay
    for (int b = tid; b < NB; b += TB4) {
        g_Wbp[b] = 0.0; g_Xbp[b] = 0.0;
        g_Wbt[b] = 0.0; g_Xbt[b] = 0.0;
        g_cntp[b] = 0;  g_cntt[b] = 0;
    }
    if (tid < 5) g_S[tid] = 0.0;
    if (tid == 0) { g_Pab = 0.0; g_ticket = 0u; g_sync = 0u; }
}

// ---------------------------------------------------------------------------
extern "C" void kernel_launch(void* const* d_in, const int* in_sizes, int n_in,
                              void* d_out, int out_size) {
    const float* p   = (const float*)d_in[0];  // inferences
    const int*   lab = (const int*)  d_in[1];  // labels
    const float* t   = (const float*)d_in[2];  // disco_target
    const float* w   = (const float*)d_in[3];  // weights
    float* out = (float*)d_out;
    int n = in_sizes[0];

    k_prep_uv<<<K1B, K1T>>>(p, lab, t, w, n);
    dim3 grid(GX, GY);   // 16 x 64 = 1024 blocks of 128
    k_pab<<<grid, TB4>>>(p, t, out, n);
}